// round 1
// baseline (speedup 1.0000x reference)
#include <cuda_runtime.h>
#include <math.h>

#define S_LEN    4096
#define D_MODEL  1024
#define NUM_HEADS 16
#define HEAD_DIM  64

// Scratch (allocation-free rule: __device__ globals)
__device__ float g_q[NUM_HEADS * S_LEN * HEAD_DIM];   // [h][s][d]
__device__ float g_k[NUM_HEADS * S_LEN * HEAD_DIM];
__device__ float g_v[NUM_HEADS * S_LEN * HEAD_DIM];
__device__ float g_attn[S_LEN * D_MODEL];             // [s][h*64+d]

// ---------------------------------------------------------------------------
// QKV GEMM: C[m,n] = sum_k x[m,k] * w_qkv[n,k], m in [0,4096), n in [0,3072)
// Epilogue scatters into g_q/g_k/g_v with [h][s][d] layout.
// Tiles: 64x64, BK=16, 256 threads, 4x4 per thread.
// ---------------------------------------------------------------------------
__global__ __launch_bounds__(256) void qkv_gemm_kernel(const float* __restrict__ x,
                                                       const float* __restrict__ w) {
    __shared__ float As[64][17];
    __shared__ float Bs[64][17];
    const int m0 = blockIdx.x * 64;
    const int n0 = blockIdx.y * 64;
    const int t  = threadIdx.x;
    const int tx = t & 15, ty = t >> 4;

    float acc[4][4];
#pragma unroll
    for (int i = 0; i < 4; i++)
#pragma unroll
        for (int j = 0; j < 4; j++) acc[i][j] = 0.0f;

    const float* Ag = x + (size_t)m0 * D_MODEL;
    const float* Bg = w + (size_t)n0 * D_MODEL;

    for (int k0 = 0; k0 < D_MODEL; k0 += 16) {
#pragma unroll
        for (int i = 0; i < 4; i++) {
            int idx = t + i * 256;
            int m = idx >> 4, k = idx & 15;
            As[m][k] = Ag[m * D_MODEL + k0 + k];
            Bs[m][k] = Bg[m * D_MODEL + k0 + k];
        }
        __syncthreads();
#pragma unroll
        for (int k = 0; k < 16; k++) {
            float a[4], b[4];
#pragma unroll
            for (int i = 0; i < 4; i++) a[i] = As[ty * 4 + i][k];
#pragma unroll
            for (int j = 0; j < 4; j++) b[j] = Bs[tx * 4 + j][k];
#pragma unroll
            for (int i = 0; i < 4; i++)
#pragma unroll
                for (int j = 0; j < 4; j++) acc[i][j] += a[i] * b[j];
        }
        __syncthreads();
    }

    // n = n0 + tx*4 + j; which/h constant per block (n0 multiple of 64)
    const int which = n0 >> 10;
    const int h     = (n0 >> 6) & (NUM_HEADS - 1);
    float* dst = (which == 0) ? g_q : ((which == 1) ? g_k : g_v);
#pragma unroll
    for (int i = 0; i < 4; i++) {
        int m = m0 + ty * 4 + i;
#pragma unroll
        for (int j = 0; j < 4; j++) {
            int d = tx * 4 + j;
            dst[((size_t)h * S_LEN + m) * HEAD_DIM + d] = acc[i][j];
        }
    }
}

// ---------------------------------------------------------------------------
// Flash attention (causal, online softmax).
// Grid: (S/32, H). 256 threads = 8 warps; each warp owns 4 query rows.
// Tiles: BQ=32 queries, BKV=64 keys. P tile reuses the (padded) K buffer.
// Per lane: cols c0=lane, c1=lane+32; acc dims d0=lane, d1=lane+32.
// ---------------------------------------------------------------------------
#define BQ  32
#define BKV 64

__global__ __launch_bounds__(256) void flash_attn_kernel() {
    __shared__ float Qs[BQ][HEAD_DIM];         //  8 KB (broadcast reads)
    __shared__ float Ks[BKV][HEAD_DIM + 1];    // 16.25 KB padded; reused as P
    __shared__ float Vs[BKV][HEAD_DIM];        // 16 KB (row-contig reads)

    const int qb = blockIdx.x, h = blockIdx.y;
    const int t = threadIdx.x, warp = t >> 5, lane = t & 31;
    const int c0 = lane, c1 = lane + 32;

    const float* Qg = g_q + ((size_t)h * S_LEN + qb * BQ) * HEAD_DIM;

    for (int i = t; i < BQ * HEAD_DIM; i += 256)
        Qs[i >> 6][i & 63] = Qg[i] * 0.125f;   // Hd^-0.5 pre-applied

    float m_i[4], l_i[4], acc0[4], acc1[4];
#pragma unroll
    for (int r = 0; r < 4; r++) { m_i[r] = -1e30f; l_i[r] = 0.0f; acc0[r] = 0.0f; acc1[r] = 0.0f; }

    const int kb_max = (qb * BQ + BQ - 1) / BKV;

    for (int kb = 0; kb <= kb_max; kb++) {
        const float* Kg = g_k + ((size_t)h * S_LEN + kb * BKV) * HEAD_DIM;
        const float* Vg = g_v + ((size_t)h * S_LEN + kb * BKV) * HEAD_DIM;

        __syncthreads();   // previous tile's P/V reads complete before overwrite
        for (int i = t; i < BKV * HEAD_DIM; i += 256) {
            int r = i >> 6, d = i & 63;
            Ks[r][d] = Kg[i];
            Vs[r][d] = Vg[i];
        }
        __syncthreads();

        // --- scores: s[r][{c0,c1}] = q_row . k_col  (pre-scaled q) ---
        float s0[4] = {0.f, 0.f, 0.f, 0.f}, s1[4] = {0.f, 0.f, 0.f, 0.f};
#pragma unroll 8
        for (int d = 0; d < HEAD_DIM; d++) {
            float k0 = Ks[c0][d], k1 = Ks[c1][d];
#pragma unroll
            for (int r = 0; r < 4; r++) {
                float q = Qs[warp * 4 + r][d];
                s0[r] += q * k0;
                s1[r] += q * k1;
            }
        }

        if (kb == kb_max) {    // causal mask only ever needed on last tile
#pragma unroll
            for (int r = 0; r < 4; r++) {
                int row = qb * BQ + warp * 4 + r;
                if (kb * BKV + c0 > row) s0[r] = -1e30f;
                if (kb * BKV + c1 > row) s1[r] = -1e30f;
            }
        }

        __syncthreads();       // all warps done reading Ks before P overwrites it
        float* Ps = &Ks[0][0]; // pitch HEAD_DIM+1

        // --- online softmax per row ---
#pragma unroll
        for (int r = 0; r < 4; r++) {
            float tmax = fmaxf(s0[r], s1[r]);
#pragma unroll
            for (int off = 16; off > 0; off >>= 1)
                tmax = fmaxf(tmax, __shfl_xor_sync(0xffffffffu, tmax, off));
            float m_new = fmaxf(m_i[r], tmax);
            float corr = __expf(m_i[r] - m_new);
            float p0 = __expf(s0[r] - m_new);
            float p1 = __expf(s1[r] - m_new);
            float ps = p0 + p1;
#pragma unroll
            for (int off = 16; off > 0; off >>= 1)
                ps += __shfl_xor_sync(0xffffffffu, ps, off);
            l_i[r] = l_i[r] * corr + ps;
            m_i[r] = m_new;
            acc0[r] *= corr;
            acc1[r] *= corr;
            Ps[(warp * 4 + r) * (HEAD_DIM + 1) + c0] = p0;
            Ps[(warp * 4 + r) * (HEAD_DIM + 1) + c1] = p1;
        }
        __syncwarp();          // own-warp P writes visible to own-warp reads

        // --- acc += P @ V  (each warp reads only its own P rows) ---
#pragma unroll 4
        for (int c = 0; c < BKV; c++) {
            float v0 = Vs[c][lane], v1 = Vs[c][lane + 32];
#pragma unroll
            for (int r = 0; r < 4; r++) {
                float p = Ps[(warp * 4 + r) * (HEAD_DIM + 1) + c];
                acc0[r] += p * v0;
                acc1[r] += p * v1;
            }
        }
    }

    // epilogue: normalize, write [s][h*64+d]
#pragma unroll
    for (int r = 0; r < 4; r++) {
        int row = qb * BQ + warp * 4 + r;
        float inv = 1.0f / l_i[r];
        g_attn[(size_t)row * D_MODEL + h * HEAD_DIM + lane]      = acc0[r] * inv;
        g_attn[(size_t)row * D_MODEL + h * HEAD_DIM + lane + 32] = acc1[r] * inv;
    }
}

// ---------------------------------------------------------------------------
// Output GEMM: y[m,n] = sum_k g_attn[m,k] * w_out[n,k], M=4096, N=1024
// ---------------------------------------------------------------------------
__global__ __launch_bounds__(256) void out_gemm_kernel(const float* __restrict__ w,
                                                       float* __restrict__ y) {
    __shared__ float As[64][17];
    __shared__ float Bs[64][17];
    const int m0 = blockIdx.x * 64;
    const int n0 = blockIdx.y * 64;
    const int t  = threadIdx.x;
    const int tx = t & 15, ty = t >> 4;

    float acc[4][4];
#pragma unroll
    for (int i = 0; i < 4; i++)
#pragma unroll
        for (int j = 0; j < 4; j++) acc[i][j] = 0.0f;

    const float* Ag = g_attn + (size_t)m0 * D_MODEL;
    const float* Bg = w + (size_t)n0 * D_MODEL;

    for (int k0 = 0; k0 < D_MODEL; k0 += 16) {
#pragma unroll
        for (int i = 0; i < 4; i++) {
            int idx = t + i * 256;
            int m = idx >> 4, k = idx & 15;
            As[m][k] = Ag[m * D_MODEL + k0 + k];
            Bs[m][k] = Bg[m * D_MODEL + k0 + k];
        }
        __syncthreads();
#pragma unroll
        for (int k = 0; k < 16; k++) {
            float a[4], b[4];
#pragma unroll
            for (int i = 0; i < 4; i++) a[i] = As[ty * 4 + i][k];
#pragma unroll
            for (int j = 0; j < 4; j++) b[j] = Bs[tx * 4 + j][k];
#pragma unroll
            for (int i = 0; i < 4; i++)
#pragma unroll
                for (int j = 0; j < 4; j++) acc[i][j] += a[i] * b[j];
        }
        __syncthreads();
    }

#pragma unroll
    for (int i = 0; i < 4; i++) {
        int m = m0 + ty * 4 + i;
#pragma unroll
        for (int j = 0; j < 4; j++) {
            int n = n0 + tx * 4 + j;
            y[(size_t)m * D_MODEL + n] = acc[i][j];
        }
    }
}

// ---------------------------------------------------------------------------
extern "C" void kernel_launch(void* const* d_in, const int* in_sizes, int n_in,
                              void* d_out, int out_size) {
    const float* x     = (const float*)d_in[0];
    const float* w_qkv = (const float*)d_in[1];
    const float* w_out = (const float*)d_in[2];
    float* y = (float*)d_out;

    qkv_gemm_kernel<<<dim3(S_LEN / 64, (3 * D_MODEL) / 64), 256>>>(x, w_qkv);
    flash_attn_kernel<<<dim3(S_LEN / BQ, NUM_HEADS), 256>>>();
    out_gemm_kernel<<<dim3(S_LEN / 64, D_MODEL / 64), 256>>>(w_out, y);
}

// round 2
// speedup vs baseline: 1.5487x; 1.5487x over previous
#include <cuda_runtime.h>
#include <math.h>
#include <stdint.h>

#define S_LEN    4096
#define D_MODEL  1024
#define NUM_HEADS 16
#define HEAD_DIM  64

// Scratch (allocation-free rule: __device__ globals)
__device__ float g_q[NUM_HEADS * S_LEN * HEAD_DIM];   // [h][s][d]
__device__ float g_k[NUM_HEADS * S_LEN * HEAD_DIM];
__device__ float g_v[NUM_HEADS * S_LEN * HEAD_DIM];
__device__ float g_attn[S_LEN * D_MODEL];             // [s][h*64+d]

// ---------------------------------------------------------------------------
// tf32 helpers
// ---------------------------------------------------------------------------
__device__ __forceinline__ uint32_t f2tf32(float f) {
    uint32_t u;
    asm("cvt.rna.tf32.f32 %0, %1;" : "=r"(u) : "f"(f));
    return u;
}

__device__ __forceinline__ void mma_tf32(float c[4],
                                         uint32_t a0, uint32_t a1, uint32_t a2, uint32_t a3,
                                         uint32_t b0, uint32_t b1) {
    asm volatile(
        "mma.sync.aligned.m16n8k8.row.col.f32.tf32.tf32.f32 "
        "{%0,%1,%2,%3}, {%4,%5,%6,%7}, {%8,%9}, {%0,%1,%2,%3};"
        : "+f"(c[0]), "+f"(c[1]), "+f"(c[2]), "+f"(c[3])
        : "r"(a0), "r"(a1), "r"(a2), "r"(a3), "r"(b0), "r"(b1));
}

// ---------------------------------------------------------------------------
// tf32 GEMM: C[m,n] = sum_k A[m,k] * B[n,k]   (A row-major, B row-major n x k)
// BM=128, BN=128, BK=16; 256 threads = 8 warps; warp tile 64x32.
// Smem pitch 20 floats -> 20*m mod 32 hits 8 distinct 4-aligned banks:
// fragment LDS is conflict-free. Double-buffered smem, one sync per iter.
// MODE 0: qkv scatter epilogue (N=3072). MODE 1: plain store (N=1024).
// ---------------------------------------------------------------------------
#define PITCH 20

template <int MODE>
__global__ __launch_bounds__(256) void gemm_tf32_kernel(const float* __restrict__ A,
                                                        const float* __restrict__ B,
                                                        float* __restrict__ C,
                                                        int ldk /* = 1024 */) {
    __shared__ uint32_t As[2][128 * PITCH];
    __shared__ uint32_t Bs[2][128 * PITCH];

    const int m0 = blockIdx.x * 128;
    const int n0 = blockIdx.y * 128;
    const int t = threadIdx.x;
    const int warp = t >> 5, lane = t & 31;
    const int warpM = warp >> 2, warpN = warp & 3;   // 2 x 4 warp grid
    const int g = lane >> 2, th = lane & 3;

    const float* Ag = A + (size_t)m0 * ldk;
    const float* Bg = B + (size_t)n0 * ldk;

    // loader mapping: float4 id f in [0,512): m = f>>2, kv = f&3
    const int lm0 = t >> 2, lkv = (t & 3) * 4;
    const int lm1 = (t + 256) >> 2;

    float acc[4][4][4];
#pragma unroll
    for (int mt = 0; mt < 4; mt++)
#pragma unroll
        for (int nt = 0; nt < 4; nt++)
#pragma unroll
            for (int i = 0; i < 4; i++) acc[mt][nt][i] = 0.0f;

    // ---- prologue: tile 0 -> buffer 0 ----
    {
        float4 a0 = *(const float4*)&Ag[(size_t)lm0 * ldk + lkv];
        float4 a1 = *(const float4*)&Ag[(size_t)lm1 * ldk + lkv];
        float4 b0 = *(const float4*)&Bg[(size_t)lm0 * ldk + lkv];
        float4 b1 = *(const float4*)&Bg[(size_t)lm1 * ldk + lkv];
        uint4* pa0 = (uint4*)&As[0][lm0 * PITCH + lkv];
        uint4* pa1 = (uint4*)&As[0][lm1 * PITCH + lkv];
        uint4* pb0 = (uint4*)&Bs[0][lm0 * PITCH + lkv];
        uint4* pb1 = (uint4*)&Bs[0][lm1 * PITCH + lkv];
        *pa0 = make_uint4(f2tf32(a0.x), f2tf32(a0.y), f2tf32(a0.z), f2tf32(a0.w));
        *pa1 = make_uint4(f2tf32(a1.x), f2tf32(a1.y), f2tf32(a1.z), f2tf32(a1.w));
        *pb0 = make_uint4(f2tf32(b0.x), f2tf32(b0.y), f2tf32(b0.z), f2tf32(b0.w));
        *pb1 = make_uint4(f2tf32(b1.x), f2tf32(b1.y), f2tf32(b1.z), f2tf32(b1.w));
    }
    __syncthreads();

    const int NITER = D_MODEL / 16;   // 64
    int buf = 0;

    for (int it = 0; it < NITER; it++) {
        float4 ra0, ra1, rb0, rb1;
        if (it < NITER - 1) {
            int k0 = (it + 1) * 16;
            ra0 = *(const float4*)&Ag[(size_t)lm0 * ldk + k0 + lkv];
            ra1 = *(const float4*)&Ag[(size_t)lm1 * ldk + k0 + lkv];
            rb0 = *(const float4*)&Bg[(size_t)lm0 * ldk + k0 + lkv];
            rb1 = *(const float4*)&Bg[(size_t)lm1 * ldk + k0 + lkv];
        }

#pragma unroll
        for (int ks = 0; ks < 2; ks++) {
            uint32_t af[4][4], bf[4][2];
#pragma unroll
            for (int mt = 0; mt < 4; mt++) {
                int r = warpM * 64 + mt * 16 + g;
                af[mt][0] = As[buf][r * PITCH + ks * 8 + th];
                af[mt][1] = As[buf][(r + 8) * PITCH + ks * 8 + th];
                af[mt][2] = As[buf][r * PITCH + ks * 8 + th + 4];
                af[mt][3] = As[buf][(r + 8) * PITCH + ks * 8 + th + 4];
            }
#pragma unroll
            for (int nt = 0; nt < 4; nt++) {
                int c = warpN * 32 + nt * 8 + g;
                bf[nt][0] = Bs[buf][c * PITCH + ks * 8 + th];
                bf[nt][1] = Bs[buf][c * PITCH + ks * 8 + th + 4];
            }
#pragma unroll
            for (int mt = 0; mt < 4; mt++)
#pragma unroll
                for (int nt = 0; nt < 4; nt++)
                    mma_tf32(acc[mt][nt], af[mt][0], af[mt][1], af[mt][2], af[mt][3],
                             bf[nt][0], bf[nt][1]);
        }

        if (it < NITER - 1) {
            int nb = buf ^ 1;
            uint4* pa0 = (uint4*)&As[nb][lm0 * PITCH + lkv];
            uint4* pa1 = (uint4*)&As[nb][lm1 * PITCH + lkv];
            uint4* pb0 = (uint4*)&Bs[nb][lm0 * PITCH + lkv];
            uint4* pb1 = (uint4*)&Bs[nb][lm1 * PITCH + lkv];
            *pa0 = make_uint4(f2tf32(ra0.x), f2tf32(ra0.y), f2tf32(ra0.z), f2tf32(ra0.w));
            *pa1 = make_uint4(f2tf32(ra1.x), f2tf32(ra1.y), f2tf32(ra1.z), f2tf32(ra1.w));
            *pb0 = make_uint4(f2tf32(rb0.x), f2tf32(rb0.y), f2tf32(rb0.z), f2tf32(rb0.w));
            *pb1 = make_uint4(f2tf32(rb1.x), f2tf32(rb1.y), f2tf32(rb1.z), f2tf32(rb1.w));
            __syncthreads();
            buf = nb;
        }
    }

    // ---- epilogue ----
#pragma unroll
    for (int mt = 0; mt < 4; mt++) {
#pragma unroll
        for (int nt = 0; nt < 4; nt++) {
            int row = m0 + warpM * 64 + mt * 16 + g;
            int col = n0 + warpN * 32 + nt * 8 + 2 * th;
            if (MODE == 0) {
                // qkv scatter: n -> (which, h, d)
                int which = col >> 10;
                float* dst = (which == 0) ? g_q : ((which == 1) ? g_k : g_v);
                int h = (col >> 6) & (NUM_HEADS - 1);
                int d = col & (HEAD_DIM - 1);
                float2* p0 = (float2*)&dst[((size_t)h * S_LEN + row) * HEAD_DIM + d];
                float2* p1 = (float2*)&dst[((size_t)h * S_LEN + row + 8) * HEAD_DIM + d];
                *p0 = make_float2(acc[mt][nt][0], acc[mt][nt][1]);
                *p1 = make_float2(acc[mt][nt][2], acc[mt][nt][3]);
            } else {
                float2* p0 = (float2*)&C[(size_t)row * D_MODEL + col];
                float2* p1 = (float2*)&C[(size_t)(row + 8) * D_MODEL + col];
                *p0 = make_float2(acc[mt][nt][0], acc[mt][nt][1]);
                *p1 = make_float2(acc[mt][nt][2], acc[mt][nt][3]);
            }
        }
    }
}

// ---------------------------------------------------------------------------
// Flash attention (causal, online softmax) — unchanged from R0 (passing).
// ---------------------------------------------------------------------------
#define BQ  32
#define BKV 64

__global__ __launch_bounds__(256) void flash_attn_kernel() {
    __shared__ float Qs[BQ][HEAD_DIM];
    __shared__ float Ks[BKV][HEAD_DIM + 1];
    __shared__ float Vs[BKV][HEAD_DIM];

    const int qb = blockIdx.x, h = blockIdx.y;
    const int t = threadIdx.x, warp = t >> 5, lane = t & 31;
    const int c0 = lane, c1 = lane + 32;

    const float* Qg = g_q + ((size_t)h * S_LEN + qb * BQ) * HEAD_DIM;

    for (int i = t; i < BQ * HEAD_DIM; i += 256)
        Qs[i >> 6][i & 63] = Qg[i] * 0.125f;

    float m_i[4], l_i[4], acc0[4], acc1[4];
#pragma unroll
    for (int r = 0; r < 4; r++) { m_i[r] = -1e30f; l_i[r] = 0.0f; acc0[r] = 0.0f; acc1[r] = 0.0f; }

    const int kb_max = (qb * BQ + BQ - 1) / BKV;

    for (int kb = 0; kb <= kb_max; kb++) {
        const float* Kg = g_k + ((size_t)h * S_LEN + kb * BKV) * HEAD_DIM;
        const float* Vg = g_v + ((size_t)h * S_LEN + kb * BKV) * HEAD_DIM;

        __syncthreads();
        for (int i = t; i < BKV * HEAD_DIM; i += 256) {
            int r = i >> 6, d = i & 63;
            Ks[r][d] = Kg[i];
            Vs[r][d] = Vg[i];
        }
        __syncthreads();

        float s0[4] = {0.f, 0.f, 0.f, 0.f}, s1[4] = {0.f, 0.f, 0.f, 0.f};
#pragma unroll 8
        for (int d = 0; d < HEAD_DIM; d++) {
            float k0 = Ks[c0][d], k1 = Ks[c1][d];
#pragma unroll
            for (int r = 0; r < 4; r++) {
                float q = Qs[warp * 4 + r][d];
                s0[r] += q * k0;
                s1[r] += q * k1;
            }
        }

        if (kb == kb_max) {
#pragma unroll
            for (int r = 0; r < 4; r++) {
                int row = qb * BQ + warp * 4 + r;
                if (kb * BKV + c0 > row) s0[r] = -1e30f;
                if (kb * BKV + c1 > row) s1[r] = -1e30f;
            }
        }

        __syncthreads();
        float* Ps = &Ks[0][0];

#pragma unroll
        for (int r = 0; r < 4; r++) {
            float tmax = fmaxf(s0[r], s1[r]);
#pragma unroll
            for (int off = 16; off > 0; off >>= 1)
                tmax = fmaxf(tmax, __shfl_xor_sync(0xffffffffu, tmax, off));
            float m_new = fmaxf(m_i[r], tmax);
            float corr = __expf(m_i[r] - m_new);
            float p0 = __expf(s0[r] - m_new);
            float p1 = __expf(s1[r] - m_new);
            float ps = p0 + p1;
#pragma unroll
            for (int off = 16; off > 0; off >>= 1)
                ps += __shfl_xor_sync(0xffffffffu, ps, off);
            l_i[r] = l_i[r] * corr + ps;
            m_i[r] = m_new;
            acc0[r] *= corr;
            acc1[r] *= corr;
            Ps[(warp * 4 + r) * (HEAD_DIM + 1) + c0] = p0;
            Ps[(warp * 4 + r) * (HEAD_DIM + 1) + c1] = p1;
        }
        __syncwarp();

#pragma unroll 4
        for (int c = 0; c < BKV; c++) {
            float v0 = Vs[c][lane], v1 = Vs[c][lane + 32];
#pragma unroll
            for (int r = 0; r < 4; r++) {
                float p = Ps[(warp * 4 + r) * (HEAD_DIM + 1) + c];
                acc0[r] += p * v0;
                acc1[r] += p * v1;
            }
        }
    }

#pragma unroll
    for (int r = 0; r < 4; r++) {
        int row = qb * BQ + warp * 4 + r;
        float inv = 1.0f / l_i[r];
        g_attn[(size_t)row * D_MODEL + h * HEAD_DIM + lane]      = acc0[r] * inv;
        g_attn[(size_t)row * D_MODEL + h * HEAD_DIM + lane + 32] = acc1[r] * inv;
    }
}

// ---------------------------------------------------------------------------
extern "C" void kernel_launch(void* const* d_in, const int* in_sizes, int n_in,
                              void* d_out, int out_size) {
    const float* x     = (const float*)d_in[0];
    const float* w_qkv = (const float*)d_in[1];
    const float* w_out = (const float*)d_in[2];
    float* y = (float*)d_out;

    // QKV: M=4096, N=3072
    gemm_tf32_kernel<0><<<dim3(S_LEN / 128, (3 * D_MODEL) / 128), 256>>>(x, w_qkv, nullptr, D_MODEL);
    flash_attn_kernel<<<dim3(S_LEN / BQ, NUM_HEADS), 256>>>();

    // out: A = g_attn (device global), M=4096, N=1024
    float* attn_ptr;
    cudaGetSymbolAddress((void**)&attn_ptr, g_attn);
    gemm_tf32_kernel<1><<<dim3(S_LEN / 128, D_MODEL / 128), 256>>>(attn_ptr, w_out, y, D_MODEL);
}

// round 3
// speedup vs baseline: 3.9712x; 2.5642x over previous
#include <cuda_runtime.h>
#include <math.h>
#include <stdint.h>

#define S_LEN    4096
#define D_MODEL  1024
#define NUM_HEADS 16
#define HEAD_DIM  64

// Scratch (allocation-free rule: __device__ globals)
__device__ float g_q[NUM_HEADS * S_LEN * HEAD_DIM];   // [h][s][d]
__device__ float g_k[NUM_HEADS * S_LEN * HEAD_DIM];
__device__ float g_v[NUM_HEADS * S_LEN * HEAD_DIM];
__device__ float g_attn[S_LEN * D_MODEL];             // [s][h*64+d]

// ---------------------------------------------------------------------------
// tf32 helpers
// ---------------------------------------------------------------------------
__device__ __forceinline__ uint32_t f2tf32(float f) {
    uint32_t u;
    asm("cvt.rna.tf32.f32 %0, %1;" : "=r"(u) : "f"(f));
    return u;
}

__device__ __forceinline__ void mma_tf32(float c[4],
                                         uint32_t a0, uint32_t a1, uint32_t a2, uint32_t a3,
                                         uint32_t b0, uint32_t b1) {
    asm volatile(
        "mma.sync.aligned.m16n8k8.row.col.f32.tf32.tf32.f32 "
        "{%0,%1,%2,%3}, {%4,%5,%6,%7}, {%8,%9}, {%0,%1,%2,%3};"
        : "+f"(c[0]), "+f"(c[1]), "+f"(c[2]), "+f"(c[3])
        : "r"(a0), "r"(a1), "r"(a2), "r"(a3), "r"(b0), "r"(b1));
}

// ---------------------------------------------------------------------------
// tf32 GEMM (unchanged from R1): C[m,n] = sum_k A[m,k]*B[n,k]
// ---------------------------------------------------------------------------
#define PITCH 20

template <int MODE>
__global__ __launch_bounds__(256) void gemm_tf32_kernel(const float* __restrict__ A,
                                                        const float* __restrict__ B,
                                                        float* __restrict__ C,
                                                        int ldk) {
    __shared__ uint32_t As[2][128 * PITCH];
    __shared__ uint32_t Bs[2][128 * PITCH];

    const int m0 = blockIdx.x * 128;
    const int n0 = blockIdx.y * 128;
    const int t = threadIdx.x;
    const int warp = t >> 5, lane = t & 31;
    const int warpM = warp >> 2, warpN = warp & 3;
    const int g = lane >> 2, th = lane & 3;

    const float* Ag = A + (size_t)m0 * ldk;
    const float* Bg = B + (size_t)n0 * ldk;

    const int lm0 = t >> 2, lkv = (t & 3) * 4;
    const int lm1 = (t + 256) >> 2;

    float acc[4][4][4];
#pragma unroll
    for (int mt = 0; mt < 4; mt++)
#pragma unroll
        for (int nt = 0; nt < 4; nt++)
#pragma unroll
            for (int i = 0; i < 4; i++) acc[mt][nt][i] = 0.0f;

    {
        float4 a0 = *(const float4*)&Ag[(size_t)lm0 * ldk + lkv];
        float4 a1 = *(const float4*)&Ag[(size_t)lm1 * ldk + lkv];
        float4 b0 = *(const float4*)&Bg[(size_t)lm0 * ldk + lkv];
        float4 b1 = *(const float4*)&Bg[(size_t)lm1 * ldk + lkv];
        *(uint4*)&As[0][lm0 * PITCH + lkv] = make_uint4(f2tf32(a0.x), f2tf32(a0.y), f2tf32(a0.z), f2tf32(a0.w));
        *(uint4*)&As[0][lm1 * PITCH + lkv] = make_uint4(f2tf32(a1.x), f2tf32(a1.y), f2tf32(a1.z), f2tf32(a1.w));
        *(uint4*)&Bs[0][lm0 * PITCH + lkv] = make_uint4(f2tf32(b0.x), f2tf32(b0.y), f2tf32(b0.z), f2tf32(b0.w));
        *(uint4*)&Bs[0][lm1 * PITCH + lkv] = make_uint4(f2tf32(b1.x), f2tf32(b1.y), f2tf32(b1.z), f2tf32(b1.w));
    }
    __syncthreads();

    const int NITER = D_MODEL / 16;
    int buf = 0;

    for (int it = 0; it < NITER; it++) {
        float4 ra0, ra1, rb0, rb1;
        if (it < NITER - 1) {
            int k0 = (it + 1) * 16;
            ra0 = *(const float4*)&Ag[(size_t)lm0 * ldk + k0 + lkv];
            ra1 = *(const float4*)&Ag[(size_t)lm1 * ldk + k0 + lkv];
            rb0 = *(const float4*)&Bg[(size_t)lm0 * ldk + k0 + lkv];
            rb1 = *(const float4*)&Bg[(size_t)lm1 * ldk + k0 + lkv];
        }

#pragma unroll
        for (int ks = 0; ks < 2; ks++) {
            uint32_t af[4][4], bf[4][2];
#pragma unroll
            for (int mt = 0; mt < 4; mt++) {
                int r = warpM * 64 + mt * 16 + g;
                af[mt][0] = As[buf][r * PITCH + ks * 8 + th];
                af[mt][1] = As[buf][(r + 8) * PITCH + ks * 8 + th];
                af[mt][2] = As[buf][r * PITCH + ks * 8 + th + 4];
                af[mt][3] = As[buf][(r + 8) * PITCH + ks * 8 + th + 4];
            }
#pragma unroll
            for (int nt = 0; nt < 4; nt++) {
                int c = warpN * 32 + nt * 8 + g;
                bf[nt][0] = Bs[buf][c * PITCH + ks * 8 + th];
                bf[nt][1] = Bs[buf][c * PITCH + ks * 8 + th + 4];
            }
#pragma unroll
            for (int mt = 0; mt < 4; mt++)
#pragma unroll
                for (int nt = 0; nt < 4; nt++)
                    mma_tf32(acc[mt][nt], af[mt][0], af[mt][1], af[mt][2], af[mt][3],
                             bf[nt][0], bf[nt][1]);
        }

        if (it < NITER - 1) {
            int nb = buf ^ 1;
            *(uint4*)&As[nb][lm0 * PITCH + lkv] = make_uint4(f2tf32(ra0.x), f2tf32(ra0.y), f2tf32(ra0.z), f2tf32(ra0.w));
            *(uint4*)&As[nb][lm1 * PITCH + lkv] = make_uint4(f2tf32(ra1.x), f2tf32(ra1.y), f2tf32(ra1.z), f2tf32(ra1.w));
            *(uint4*)&Bs[nb][lm0 * PITCH + lkv] = make_uint4(f2tf32(rb0.x), f2tf32(rb0.y), f2tf32(rb0.z), f2tf32(rb0.w));
            *(uint4*)&Bs[nb][lm1 * PITCH + lkv] = make_uint4(f2tf32(rb1.x), f2tf32(rb1.y), f2tf32(rb1.z), f2tf32(rb1.w));
            __syncthreads();
            buf = nb;
        }
    }

#pragma unroll
    for (int mt = 0; mt < 4; mt++) {
#pragma unroll
        for (int nt = 0; nt < 4; nt++) {
            int row = m0 + warpM * 64 + mt * 16 + g;
            int col = n0 + warpN * 32 + nt * 8 + 2 * th;
            if (MODE == 0) {
                int which = col >> 10;
                float* dst = (which == 0) ? g_q : ((which == 1) ? g_k : g_v);
                int h = (col >> 6) & (NUM_HEADS - 1);
                int d = col & (HEAD_DIM - 1);
                *(float2*)&dst[((size_t)h * S_LEN + row) * HEAD_DIM + d] =
                    make_float2(acc[mt][nt][0], acc[mt][nt][1]);
                *(float2*)&dst[((size_t)h * S_LEN + row + 8) * HEAD_DIM + d] =
                    make_float2(acc[mt][nt][2], acc[mt][nt][3]);
            } else {
                *(float2*)&C[(size_t)row * D_MODEL + col] =
                    make_float2(acc[mt][nt][0], acc[mt][nt][1]);
                *(float2*)&C[(size_t)(row + 8) * D_MODEL + col] =
                    make_float2(acc[mt][nt][2], acc[mt][nt][3]);
            }
        }
    }
}

// ---------------------------------------------------------------------------
// Flash attention with tf32 mma.
// 128 threads = 4 warps. BQ=64 (warp owns 16 rows), BKV=64.
// Smem tiles pre-converted to tf32, pitch 68 (68 mod 32 = 4 -> conflict-free
// fragment LDS: banks 4g+th all distinct).
// P reuses K smem after S compute (warp-local 16-row region).
// ---------------------------------------------------------------------------
#define AP 68

__global__ __launch_bounds__(128) void flash_attn_mma_kernel() {
    __shared__ uint32_t Ks[64 * AP];   // K tile; reused as P tile
    __shared__ uint32_t Vs[64 * AP];   // V tile

    const int qb = (int)gridDim.x - 1 - (int)blockIdx.x;  // longest blocks first
    const int h  = blockIdx.y;
    const int t = threadIdx.x, warp = t >> 5, lane = t & 31;
    const int g = lane >> 2, th = lane & 3;
    const int qbase = qb * 64;
    const int row0 = qbase + warp * 16 + g;     // second row = row0 + 8

    // ---- Q fragments in registers (scaled by Hd^-0.5, tf32) ----
    uint32_t qf[8][4];
    {
        const float* qr0 = g_q + ((size_t)h * S_LEN + row0) * HEAD_DIM;
        const float* qr1 = qr0 + 8 * HEAD_DIM;
#pragma unroll
        for (int kc = 0; kc < 8; kc++) {
            qf[kc][0] = f2tf32(qr0[kc * 8 + th] * 0.125f);
            qf[kc][1] = f2tf32(qr1[kc * 8 + th] * 0.125f);
            qf[kc][2] = f2tf32(qr0[kc * 8 + th + 4] * 0.125f);
            qf[kc][3] = f2tf32(qr1[kc * 8 + th + 4] * 0.125f);
        }
    }

    float acc[8][4];
#pragma unroll
    for (int n = 0; n < 8; n++)
#pragma unroll
        for (int i = 0; i < 4; i++) acc[n][i] = 0.0f;
    float m0 = -1e30f, m1 = -1e30f, l0 = 0.0f, l1 = 0.0f;

    const float* Kg = g_k + (size_t)h * S_LEN * HEAD_DIM;
    const float* Vg = g_v + (size_t)h * S_LEN * HEAD_DIM;

    for (int kb = 0; kb <= qb; kb++) {
        __syncthreads();   // prior V / P(K-region) reads complete

        // ---- cooperative K/V tile load + tf32 convert ----
#pragma unroll
        for (int i = 0; i < 8; i++) {
            int f = t + i * 128;             // 0..1023 float4 ids
            int r = f >> 4, c = (f & 15) * 4;
            const float4 k4 = *(const float4*)&Kg[((size_t)(kb * 64 + r)) * HEAD_DIM + c];
            const float4 v4 = *(const float4*)&Vg[((size_t)(kb * 64 + r)) * HEAD_DIM + c];
            *(uint4*)&Ks[r * AP + c] = make_uint4(f2tf32(k4.x), f2tf32(k4.y), f2tf32(k4.z), f2tf32(k4.w));
            *(uint4*)&Vs[r * AP + c] = make_uint4(f2tf32(v4.x), f2tf32(v4.y), f2tf32(v4.z), f2tf32(v4.w));
        }
        __syncthreads();

        // ---- S = Q @ K^T : sc[nt] covers cols kb*64 + nt*8 .. +7 ----
        float sc[8][4];
#pragma unroll
        for (int n = 0; n < 8; n++)
#pragma unroll
            for (int i = 0; i < 4; i++) sc[n][i] = 0.0f;

#pragma unroll
        for (int kc = 0; kc < 8; kc++) {
#pragma unroll
            for (int nt = 0; nt < 8; nt++) {
                uint32_t b0 = Ks[(nt * 8 + g) * AP + kc * 8 + th];
                uint32_t b1 = Ks[(nt * 8 + g) * AP + kc * 8 + th + 4];
                mma_tf32(sc[nt], qf[kc][0], qf[kc][1], qf[kc][2], qf[kc][3], b0, b1);
            }
        }

        // ---- causal mask (diagonal tile only) ----
        if (kb == qb) {
#pragma unroll
            for (int nt = 0; nt < 8; nt++) {
                int c0 = kb * 64 + nt * 8 + 2 * th;
                if (c0 > row0)         sc[nt][0] = -1e30f;
                if (c0 + 1 > row0)     sc[nt][1] = -1e30f;
                if (c0 > row0 + 8)     sc[nt][2] = -1e30f;
                if (c0 + 1 > row0 + 8) sc[nt][3] = -1e30f;
            }
        }

        // ---- online softmax ----
        float tm0 = -1e30f, tm1 = -1e30f;
#pragma unroll
        for (int nt = 0; nt < 8; nt++) {
            tm0 = fmaxf(tm0, fmaxf(sc[nt][0], sc[nt][1]));
            tm1 = fmaxf(tm1, fmaxf(sc[nt][2], sc[nt][3]));
        }
        tm0 = fmaxf(tm0, __shfl_xor_sync(0xffffffffu, tm0, 1));
        tm0 = fmaxf(tm0, __shfl_xor_sync(0xffffffffu, tm0, 2));
        tm1 = fmaxf(tm1, __shfl_xor_sync(0xffffffffu, tm1, 1));
        tm1 = fmaxf(tm1, __shfl_xor_sync(0xffffffffu, tm1, 2));

        float mn0 = fmaxf(m0, tm0), mn1 = fmaxf(m1, tm1);
        float corr0 = __expf(m0 - mn0), corr1 = __expf(m1 - mn1);

        float ps0 = 0.0f, ps1 = 0.0f;
#pragma unroll
        for (int nt = 0; nt < 8; nt++) {
            sc[nt][0] = __expf(sc[nt][0] - mn0);
            sc[nt][1] = __expf(sc[nt][1] - mn0);
            sc[nt][2] = __expf(sc[nt][2] - mn1);
            sc[nt][3] = __expf(sc[nt][3] - mn1);
            ps0 += sc[nt][0] + sc[nt][1];
            ps1 += sc[nt][2] + sc[nt][3];
        }
        ps0 += __shfl_xor_sync(0xffffffffu, ps0, 1);
        ps0 += __shfl_xor_sync(0xffffffffu, ps0, 2);
        ps1 += __shfl_xor_sync(0xffffffffu, ps1, 1);
        ps1 += __shfl_xor_sync(0xffffffffu, ps1, 2);

        l0 = l0 * corr0 + ps0;  m0 = mn0;
        l1 = l1 * corr1 + ps1;  m1 = mn1;
#pragma unroll
        for (int nt = 0; nt < 8; nt++) {
            acc[nt][0] *= corr0;  acc[nt][1] *= corr0;
            acc[nt][2] *= corr1;  acc[nt][3] *= corr1;
        }

        // ---- P -> smem (reuse K region; warp-local 16 rows) ----
        __syncthreads();   // all warps done reading K fragments
        uint32_t* Ps = &Ks[warp * 16 * AP];
#pragma unroll
        for (int nt = 0; nt < 8; nt++) {
            Ps[g * AP + nt * 8 + 2 * th]           = f2tf32(sc[nt][0]);
            Ps[g * AP + nt * 8 + 2 * th + 1]       = f2tf32(sc[nt][1]);
            Ps[(g + 8) * AP + nt * 8 + 2 * th]     = f2tf32(sc[nt][2]);
            Ps[(g + 8) * AP + nt * 8 + 2 * th + 1] = f2tf32(sc[nt][3]);
        }
        __syncwarp();

        // ---- acc += P @ V ----
#pragma unroll
        for (int kc = 0; kc < 8; kc++) {
            uint32_t a0 = Ps[g * AP + kc * 8 + th];
            uint32_t a1 = Ps[(g + 8) * AP + kc * 8 + th];
            uint32_t a2 = Ps[g * AP + kc * 8 + th + 4];
            uint32_t a3 = Ps[(g + 8) * AP + kc * 8 + th + 4];
#pragma unroll
            for (int nt2 = 0; nt2 < 8; nt2++) {
                uint32_t b0 = Vs[(kc * 8 + th) * AP + nt2 * 8 + g];
                uint32_t b1 = Vs[(kc * 8 + th + 4) * AP + nt2 * 8 + g];
                mma_tf32(acc[nt2], a0, a1, a2, a3, b0, b1);
            }
        }
    }

    // ---- epilogue: normalize, write [s][h*64+d] ----
    float inv0 = 1.0f / l0, inv1 = 1.0f / l1;
#pragma unroll
    for (int nt2 = 0; nt2 < 8; nt2++) {
        int col = h * HEAD_DIM + nt2 * 8 + 2 * th;
        *(float2*)&g_attn[(size_t)row0 * D_MODEL + col] =
            make_float2(acc[nt2][0] * inv0, acc[nt2][1] * inv0);
        *(float2*)&g_attn[(size_t)(row0 + 8) * D_MODEL + col] =
            make_float2(acc[nt2][2] * inv1, acc[nt2][3] * inv1);
    }
}

// ---------------------------------------------------------------------------
extern "C" void kernel_launch(void* const* d_in, const int* in_sizes, int n_in,
                              void* d_out, int out_size) {
    const float* x     = (const float*)d_in[0];
    const float* w_qkv = (const float*)d_in[1];
    const float* w_out = (const float*)d_in[2];
    float* y = (float*)d_out;

    gemm_tf32_kernel<0><<<dim3(S_LEN / 128, (3 * D_MODEL) / 128), 256>>>(x, w_qkv, nullptr, D_MODEL);

    flash_attn_mma_kernel<<<dim3(S_LEN / 64, NUM_HEADS), 128>>>();

    float* attn_ptr;
    cudaGetSymbolAddress((void**)&attn_ptr, g_attn);
    gemm_tf32_kernel<1><<<dim3(S_LEN / 128, D_MODEL / 128), 256>>>(attn_ptr, w_out, y, D_MODEL);
}